// round 4
// baseline (speedup 1.0000x reference)
#include <cuda_runtime.h>
#include <cuda_bf16.h>

// Quanvolution (2x2, 4 qubits, RY encode + RY params + CNOT ring, <Z_q>).
//
// Closed form per output pixel (x,y), patch a00,a01,a10,a11, weights w0..w3:
//   Zq = cos(pi*a_q + w_q)
//   ch0 = Z1*Z2*Z3, ch1 = Z0*Z1, ch2 = Z0*Z1*Z2, ch3 = Z0*Z1*Z2*Z3
//
// R4: weight-folded Z tables in smem (q1/q3 tables column-shifted so all four
// operands of a pixel share one column index), 4-pixel strips per thread with
// aligned LDS.128, div-free loader, single kernel.

#define H_IN 224
#define W_IN 224
#define L_OUT 223          // H_IN - 2 + 1
#define TILE 32
#define HROWS 33           // halo rows
#define CPAD 36            // row stride in floats; 36*4=144B ≡ 0 mod 16 -> aligned float4
#define PI_F 3.14159265358979323846f

__global__ __launch_bounds__(256) void quanv_main_kernel(
    const float* __restrict__ in,   // (64,1,224,224)
    const float* __restrict__ w,    // (1,4)
    float* __restrict__ out)        // (64,4,223,223)
{
    __shared__ float Zt0[HROWS][CPAD];   // Z@w0 of element (r,c)
    __shared__ float Zt1[HROWS][CPAD];   // Z@w1 of element (r,c+1)  [shifted]
    __shared__ float Zt2[HROWS][CPAD];   // Z@w2 of element (r,c)
    __shared__ float Zt3[HROWS][CPAD];   // Z@w3 of element (r,c+1)  [shifted]
    __shared__ float cws[4], sws[4];

    const int tid = threadIdx.x;
    const int b  = blockIdx.z;
    const int x0 = blockIdx.y * TILE;
    const int y0 = blockIdx.x * TILE;

    if (tid < 4) {
        float s, c;
        __sincosf(__ldg(&w[tid]), &s, &c);
        cws[tid] = c; sws[tid] = s;
    }
    __syncthreads();

    const float cw0 = cws[0], sw0 = sws[0];
    const float cw1 = cws[1], sw1 = sws[1];
    const float cw2 = cws[2], sw2 = sws[2];
    const float cw3 = cws[3], sw3 = sws[3];

    const float* inb = in + (size_t)b * (H_IN * W_IN);
    const int lane = tid & 31;

    // Main halo load: source cols 0..31 by lane, rows 0..32 by (tid>>5)+8k.
    for (int r = tid >> 5; r < HROWS; r += 8) {
        const int gx = x0 + r, gy = y0 + lane;
        float v = 0.0f;
        if (gx < H_IN && gy < W_IN) v = __ldg(&inb[gx * W_IN + gy]);
        float s, c;
        __sincosf(v * PI_F, &s, &c);
        Zt0[r][lane] = fmaf(-s, sw0, c * cw0);
        Zt2[r][lane] = fmaf(-s, sw2, c * cw2);
        if (lane) {
            Zt1[r][lane - 1] = fmaf(-s, sw1, c * cw1);
            Zt3[r][lane - 1] = fmaf(-s, sw3, c * cw3);
        }
    }
    // Source col 32 (feeds only the shifted tables at col 31).
    if (tid < HROWS) {
        const int gx = x0 + tid, gy = y0 + 32;
        float v = 0.0f;
        if (gx < H_IN && gy < W_IN) v = __ldg(&inb[gx * W_IN + gy]);
        float s, c;
        __sincosf(v * PI_F, &s, &c);
        Zt1[tid][31] = fmaf(-s, sw1, c * cw1);
        Zt3[tid][31] = fmaf(-s, sw3, c * cw3);
    }
    __syncthreads();

    // One 4-pixel strip per thread: 256 threads cover the 32x32 tile.
    const int yg = tid & 7;         // column quad 0..7
    const int r  = tid >> 3;        // row 0..31
    const int yb = yg << 2;         // local col base
    const int x  = x0 + r;
    const int y  = y0 + yb;

    const float4 Z0 = *reinterpret_cast<const float4*>(&Zt0[r    ][yb]);
    const float4 Z1 = *reinterpret_cast<const float4*>(&Zt1[r    ][yb]);
    const float4 Z2 = *reinterpret_cast<const float4*>(&Zt2[r + 1][yb]);
    const float4 Z3 = *reinterpret_cast<const float4*>(&Zt3[r + 1][yb]);

    const float z0[4] = {Z0.x, Z0.y, Z0.z, Z0.w};
    const float z1[4] = {Z1.x, Z1.y, Z1.z, Z1.w};
    const float z2[4] = {Z2.x, Z2.y, Z2.z, Z2.w};
    const float z3[4] = {Z3.x, Z3.y, Z3.z, Z3.w};

    const size_t plane = (size_t)L_OUT * L_OUT;
    float* o = out + (size_t)b * 4 * plane + (size_t)x * L_OUT + y;

    if (x < L_OUT) {
        if (y + 4 <= L_OUT) {
            #pragma unroll
            for (int j = 0; j < 4; j++) {
                const float p01 = z0[j] * z1[j];
                const float p23 = z2[j] * z3[j];
                o[j]             = z1[j] * p23;    // ch0
                o[plane + j]     = p01;            // ch1
                o[2 * plane + j] = p01 * z2[j];    // ch2
                o[3 * plane + j] = p01 * p23;      // ch3
            }
        } else {
            #pragma unroll
            for (int j = 0; j < 4; j++) {
                if (y + j < L_OUT) {
                    const float p01 = z0[j] * z1[j];
                    const float p23 = z2[j] * z3[j];
                    o[j]             = z1[j] * p23;
                    o[plane + j]     = p01;
                    o[2 * plane + j] = p01 * z2[j];
                    o[3 * plane + j] = p01 * p23;
                }
            }
        }
    }
}

extern "C" void kernel_launch(void* const* d_in, const int* in_sizes, int n_in,
                              void* d_out, int out_size) {
    const float* inputs = (const float*)d_in[0];   // (64,1,224,224) float32
    const float* weight = (const float*)d_in[1];   // (1,4) float32
    float* out = (float*)d_out;                    // (64,4,223,223) float32

    dim3 grid((L_OUT + TILE - 1) / TILE,   // 7 (y tiles)
              (L_OUT + TILE - 1) / TILE,   // 7 (x tiles)
              64);                          // batch
    quanv_main_kernel<<<grid, 256>>>(inputs, weight, out);
}

// round 5
// speedup vs baseline: 2.1402x; 2.1402x over previous
#include <cuda_runtime.h>
#include <cuda_bf16.h>

// Quanvolution (2x2, 4 qubits, RY encode + RY params + CNOT ring, <Z_q>).
//
// Closed form per output pixel (x,y), patch a(x,y),a(x,y+1),a(x+1,y),a(x+1,y+1):
//   Zq = cos(pi*a_q + w_q)
//   ch0 = Z1*Z2*Z3, ch1 = Z0*Z1, ch2 = Z0*Z1*Z2, ch3 = Z0*Z1*Z2*Z3
//
// R5: weight-folded Z tables stored TRANSPOSED (column-major, rows contiguous)
// with T1/T3 column-shifted and T2/T3 row-shifted, so each thread's 4-row
// pixel strip needs exactly 4 aligned LDS.128 while warp lanes stay mapped to
// consecutive y -> fully coalesced STG (the R4 failure mode, fixed).

#define H_IN 224
#define W_IN 224
#define L_OUT 223
#define TILE 32
#define RPAD 36            // row-dim stride (floats); 4c mod 32 pattern -> conflict-free 128b
#define PI_F 3.14159265358979323846f

__global__ __launch_bounds__(256) void quanv_main_kernel(
    const float* __restrict__ in,   // (64,1,224,224)
    const float* __restrict__ w,    // (1,4)
    float* __restrict__ out)        // (64,4,223,223)
{
    // Tq[c][r]:
    //   T0[c][r] = Z_w0(row r,   col c)
    //   T1[c][r] = Z_w1(row r,   col c+1)
    //   T2[c][r] = Z_w2(row r+1, col c)
    //   T3[c][r] = Z_w3(row r+1, col c+1)
    __shared__ float T0[TILE][RPAD];
    __shared__ float T1[TILE][RPAD];
    __shared__ float T2[TILE][RPAD];
    __shared__ float T3[TILE][RPAD];

    const int tid = threadIdx.x;
    const int b  = blockIdx.z;
    const int x0 = blockIdx.y * TILE;
    const int y0 = blockIdx.x * TILE;

    // Per-thread weight trig via MUFU (avoids an extra barrier; broadcast LDG).
    float cw0, sw0, cw1, sw1, cw2, sw2, cw3, sw3;
    __sincosf(__ldg(&w[0]), &sw0, &cw0);
    __sincosf(__ldg(&w[1]), &sw1, &cw1);
    __sincosf(__ldg(&w[2]), &sw2, &cw2);
    __sincosf(__ldg(&w[3]), &sw3, &cw3);

    const float* inb = in + (size_t)b * (H_IN * W_IN);

    const int c  = tid & 31;   // column within tile (lane -> consecutive y)
    const int g  = tid >> 5;   // 0..7
    const int rb = g << 2;     // row-strip base: 0,4,...,28

    // ---- Loader: source column c, source rows rb..rb+4 (5, one overlap) ----
    {
        float zc[5], zs[5];
        #pragma unroll
        for (int j = 0; j < 5; j++) {
            const int gx = x0 + rb + j, gy = y0 + c;
            float v = (gx < H_IN && gy < W_IN) ? __ldg(&inb[gx * W_IN + gy]) : 0.0f;
            __sincosf(v * PI_F, &zs[j], &zc[j]);
        }
        float4 t;
        t = make_float4(fmaf(-zs[0], sw0, zc[0] * cw0), fmaf(-zs[1], sw0, zc[1] * cw0),
                        fmaf(-zs[2], sw0, zc[2] * cw0), fmaf(-zs[3], sw0, zc[3] * cw0));
        *reinterpret_cast<float4*>(&T0[c][rb]) = t;
        t = make_float4(fmaf(-zs[1], sw2, zc[1] * cw2), fmaf(-zs[2], sw2, zc[2] * cw2),
                        fmaf(-zs[3], sw2, zc[3] * cw2), fmaf(-zs[4], sw2, zc[4] * cw2));
        *reinterpret_cast<float4*>(&T2[c][rb]) = t;
        if (c > 0) {
            t = make_float4(fmaf(-zs[0], sw1, zc[0] * cw1), fmaf(-zs[1], sw1, zc[1] * cw1),
                            fmaf(-zs[2], sw1, zc[2] * cw1), fmaf(-zs[3], sw1, zc[3] * cw1));
            *reinterpret_cast<float4*>(&T1[c - 1][rb]) = t;
            t = make_float4(fmaf(-zs[1], sw3, zc[1] * cw3), fmaf(-zs[2], sw3, zc[2] * cw3),
                            fmaf(-zs[3], sw3, zc[3] * cw3), fmaf(-zs[4], sw3, zc[4] * cw3));
            *reinterpret_cast<float4*>(&T3[c - 1][rb]) = t;
        }
    }
    // ---- Extra pass: source column 32 feeds T1[31], T3[31] ----
    if (tid < 8) {
        const int rb2 = tid << 2;
        float zc[5], zs[5];
        #pragma unroll
        for (int j = 0; j < 5; j++) {
            const int gx = x0 + rb2 + j, gy = y0 + 32;
            float v = (gx < H_IN && gy < W_IN) ? __ldg(&inb[gx * W_IN + gy]) : 0.0f;
            __sincosf(v * PI_F, &zs[j], &zc[j]);
        }
        float4 t;
        t = make_float4(fmaf(-zs[0], sw1, zc[0] * cw1), fmaf(-zs[1], sw1, zc[1] * cw1),
                        fmaf(-zs[2], sw1, zc[2] * cw1), fmaf(-zs[3], sw1, zc[3] * cw1));
        *reinterpret_cast<float4*>(&T1[31][rb2]) = t;
        t = make_float4(fmaf(-zs[1], sw3, zc[1] * cw3), fmaf(-zs[2], sw3, zc[2] * cw3),
                        fmaf(-zs[3], sw3, zc[3] * cw3), fmaf(-zs[4], sw3, zc[4] * cw3));
        *reinterpret_cast<float4*>(&T3[31][rb2]) = t;
    }
    __syncthreads();

    // ---- Consumer: 4-row strip (rows rb..rb+3) at column c ----
    const int y = y0 + c;
    if (y >= L_OUT) return;

    const float4 Z0 = *reinterpret_cast<const float4*>(&T0[c][rb]);
    const float4 Z1 = *reinterpret_cast<const float4*>(&T1[c][rb]);
    const float4 Z2 = *reinterpret_cast<const float4*>(&T2[c][rb]);
    const float4 Z3 = *reinterpret_cast<const float4*>(&T3[c][rb]);

    const float z0[4] = {Z0.x, Z0.y, Z0.z, Z0.w};
    const float z1[4] = {Z1.x, Z1.y, Z1.z, Z1.w};
    const float z2[4] = {Z2.x, Z2.y, Z2.z, Z2.w};
    const float z3[4] = {Z3.x, Z3.y, Z3.z, Z3.w};

    const size_t plane = (size_t)L_OUT * L_OUT;
    float* o = out + (size_t)b * 4 * plane + (size_t)(x0 + rb) * L_OUT + y;

    #pragma unroll
    for (int j = 0; j < 4; j++) {
        if (x0 + rb + j < L_OUT) {
            const float p01 = z0[j] * z1[j];
            const float p23 = z2[j] * z3[j];
            o[0]         = z1[j] * p23;   // ch0 = Z1 Z2 Z3
            o[plane]     = p01;           // ch1 = Z0 Z1
            o[2 * plane] = p01 * z2[j];   // ch2 = Z0 Z1 Z2
            o[3 * plane] = p01 * p23;     // ch3 = Z0 Z1 Z2 Z3
        }
        o += L_OUT;
    }
}

extern "C" void kernel_launch(void* const* d_in, const int* in_sizes, int n_in,
                              void* d_out, int out_size) {
    const float* inputs = (const float*)d_in[0];   // (64,1,224,224) float32
    const float* weight = (const float*)d_in[1];   // (1,4) float32
    float* out = (float*)d_out;                    // (64,4,223,223) float32

    dim3 grid((L_OUT + TILE - 1) / TILE,   // 7 (y tiles)
              (L_OUT + TILE - 1) / TILE,   // 7 (x tiles)
              64);                          // batch
    quanv_main_kernel<<<grid, 256>>>(inputs, weight, out);
}